// round 2
// baseline (speedup 1.0000x reference)
#include <cuda_runtime.h>
#include <cstdint>

#define ROUNDS 64
#define HID 256
#define BATCH 65536
#define TILE_M 128
#define NTILES (BATCH / TILE_M)      // 512
#define MAT_BYTES (HID * HID)        // 65536 s8 per round matrix

// Pre-converted, pre-swizzled s8 matrices (SMEM image layout), 4 MB. Lives in L2.
__device__ __align__(128) unsigned char g_mat[ROUNDS * MAT_BYTES];

// ---------------- SMEM layout ----------------
#define OF_NOISE 0
#define OF_A0    1024
#define OF_A1    (1024 + 32768)
#define OF_B0    (1024 + 2 * 32768)
#define OF_B1    (OF_B0 + 65536)
#define SMEM_TOTAL (OF_B1 + 65536)   // 197632 bytes

// ---------------- helpers ----------------
__device__ __forceinline__ uint32_t smem_u32(const void* p) {
    uint32_t a;
    asm("{ .reg .u64 t; cvta.to.shared.u64 t, %1; cvt.u32.u64 %0, t; }" : "=r"(a) : "l"(p));
    return a;
}

// byte address inside a [rows x 256B] tile with 16B-chunk XOR swizzle
__device__ __forceinline__ uint32_t swz(uint32_t row, uint32_t col) {
    return row * 256u + ((((col >> 4) ^ (row & 7u)) << 4) | (col & 15u));
}

__device__ __forceinline__ void ldm_x4(uint32_t addr, uint32_t& r0, uint32_t& r1,
                                       uint32_t& r2, uint32_t& r3) {
    asm volatile("ldmatrix.sync.aligned.m8n8.x4.shared.b16 {%0,%1,%2,%3}, [%4];"
                 : "=r"(r0), "=r"(r1), "=r"(r2), "=r"(r3) : "r"(addr));
}

__device__ __forceinline__ void mma_s8(int* c, uint32_t a0, uint32_t a1, uint32_t a2,
                                       uint32_t a3, uint32_t b0, uint32_t b1) {
    asm volatile(
        "mma.sync.aligned.m16n8k32.row.col.s32.s8.s8.s32 "
        "{%0,%1,%2,%3}, {%4,%5,%6,%7}, {%8,%9}, {%0,%1,%2,%3};"
        : "+r"(c[0]), "+r"(c[1]), "+r"(c[2]), "+r"(c[3])
        : "r"(a0), "r"(a1), "r"(a2), "r"(a3), "r"(b0), "r"(b1));
}

__device__ __forceinline__ void issue_b(uint32_t dst, int r, int tid) {
    const unsigned char* src = g_mat + (size_t)r * MAT_BYTES;
#pragma unroll
    for (int j = 0; j < 16; j++) {
        uint32_t off = (uint32_t)(tid + (j << 8)) << 4;
        asm volatile("cp.async.cg.shared.global [%0], [%1], 16;"
                     :: "r"(dst + off), "l"(src + off) : "memory");
    }
}

// ---------------- Kernel 1: f32 matrices -> s8 pre-swizzled image ----------------
// D[m,n] = sum_k s[m,k] * M[n,k]  =>  B row n = M row n (k-contiguous). 4 bytes/thread.
__global__ void cvt_mats_kernel(const float* __restrict__ m) {
    uint32_t i = blockIdx.x * 256u + threadIdx.x;       // group of 4 elements
    const float4 v = *(const float4*)(m + (size_t)i * 4);
    uint32_t e0 = v.x > 0.5f ? 0x01u : (v.x < -0.5f ? 0xFFu : 0x00u);
    uint32_t e1 = v.y > 0.5f ? 0x01u : (v.y < -0.5f ? 0xFFu : 0x00u);
    uint32_t e2 = v.z > 0.5f ? 0x01u : (v.z < -0.5f ? 0xFFu : 0x00u);
    uint32_t e3 = v.w > 0.5f ? 0x01u : (v.w < -0.5f ? 0xFFu : 0x00u);
    uint32_t pk = e0 | (e1 << 8) | (e2 << 16) | (e3 << 24);
    uint32_t idx = i << 2;
    uint32_t r = idx >> 16, n = (idx >> 8) & 255u, k = idx & 255u;
    *(uint32_t*)(g_mat + (r << 16) + swz(n, k)) = pk;   // k%16 is 4-aligned here
}

// ---------------- Kernel 2: 64 sequential rounds per 128-row tile ----------------
__global__ __launch_bounds__(256, 1)
void tenshash_kernel(const float* __restrict__ state,
                     const float* __restrict__ noise,
                     float* __restrict__ out) {
    extern __shared__ unsigned char smem[];
    uint32_t sb = smem_u32(smem);
    int tid = threadIdx.x, w = tid >> 5, l = tid & 31;
    int* nsm = (int*)(smem + OF_NOISE);
    const int gbase = blockIdx.x * TILE_M;

    // stage noise[0]
    nsm[tid] = (int)noise[tid];

    // init A0 from state (float {0,1} -> s8), swizzled, u16-packed
    for (int i = tid; i < TILE_M * HID / 2; i += 256) {
        int row = i >> 7;
        int k = (i & 127) << 1;
        const float2 v = *(const float2*)(state + (size_t)(gbase + row) * HID + k);
        uint32_t b0 = v.x > 0.5f ? 1u : 0u;
        uint32_t b1 = v.y > 0.5f ? 1u : 0u;
        *(unsigned short*)(smem + OF_A0 + swz((uint32_t)row, (uint32_t)k)) =
            (unsigned short)(b0 | (b1 << 8));
    }

    // prologue: prefetch B for rounds 0 and 1
    issue_b(sb + OF_B0, 0, tid);
    asm volatile("cp.async.commit_group;" ::: "memory");
    issue_b(sb + OF_B1, 1, tid);
    asm volatile("cp.async.commit_group;" ::: "memory");

    // lane-invariant ldmatrix addressing pieces
    const int R0 = w << 4;                         // warp's 16-row base
    const uint32_t rowA = (uint32_t)R0 + (l & 15);
    const uint32_t sA = rowA & 7u;
    const uint32_t aRow = rowA * 256u;
    const uint32_t aHalf = (uint32_t)(l >> 4);     // chunk = 2*kk + aHalf
    const int r0loc = R0 + (l >> 2), r1loc = r0loc + 8;

#pragma unroll 1
    for (int r = 0; r < ROUNDS; r++) {
        asm volatile("cp.async.wait_group 1;" ::: "memory");
        __syncthreads();    // B[r&1] ready; A[cur]/noise staged
        const uint32_t Acur = sb + ((r & 1) ? OF_A1 : OF_A0);
        const uint32_t Anxt = sb + ((r & 1) ? OF_A0 : OF_A1);
        const uint32_t Bcur = sb + ((r & 1) ? OF_B1 : OF_B0);
        const bool last = (r == ROUNDS - 1);

#pragma unroll 1
        for (int ch = 0; ch < 4; ch++) {           // 64-col n-chunks
            int acc[8][4];
#pragma unroll
            for (int t = 0; t < 8; t++)
                acc[t][0] = acc[t][1] = acc[t][2] = acc[t][3] = 0;

#pragma unroll
            for (int kk = 0; kk < 8; kk++) {       // K = 8 x k32
                uint32_t a0, a1, a2, a3;
                ldm_x4(Acur + aRow + ((((uint32_t)(2 * kk) + aHalf) ^ sA) << 4),
                       a0, a1, a2, a3);
                uint32_t bb[16];
#pragma unroll
                for (int p = 0; p < 4; p++) {      // 2 n-tiles per ldmatrix.x4
                    uint32_t n = ((uint32_t)(8 * ch + 2 * p) << 3) +
                                 (((uint32_t)l >> 4) << 3) + (l & 7);
                    uint32_t cb = (uint32_t)(2 * kk) + (((uint32_t)l >> 3) & 1u);
                    ldm_x4(Bcur + n * 256u + ((cb ^ (n & 7u)) << 4),
                           bb[4 * p + 0], bb[4 * p + 1], bb[4 * p + 2], bb[4 * p + 3]);
                }
#pragma unroll
                for (int t = 0; t < 8; t++) {
                    int idx = 4 * (t >> 1) + 2 * (t & 1);
                    mma_s8(acc[t], a0, a1, a2, a3, bb[idx], bb[idx + 1]);
                }
            }

            // epilogue: v = (acc + noise) % 2 (C trunc == fmod), write next A / out
#pragma unroll
            for (int t = 0; t < 8; t++) {
                int col0 = (ch << 6) + (t << 3) + ((l & 3) << 1);
                int n0 = nsm[col0], n1 = nsm[col0 + 1];
                int v00 = (acc[t][0] + n0) % 2, v01 = (acc[t][1] + n1) % 2;
                int v10 = (acc[t][2] + n0) % 2, v11 = (acc[t][3] + n1) % 2;
                if (!last) {
                    *(unsigned short*)(smem + (Anxt - sb) + swz((uint32_t)r0loc, (uint32_t)col0)) =
                        (unsigned short)((v00 & 255) | ((v01 & 255) << 8));
                    *(unsigned short*)(smem + (Anxt - sb) + swz((uint32_t)r1loc, (uint32_t)col0)) =
                        (unsigned short)((v10 & 255) | ((v11 & 255) << 8));
                } else {
                    float2 o0 = make_float2((float)v00, (float)v01);
                    float2 o1 = make_float2((float)v10, (float)v11);
                    *(float2*)(out + (size_t)(gbase + r0loc) * HID + col0) = o0;
                    *(float2*)(out + (size_t)(gbase + r1loc) * HID + col0) = o1;
                }
            }
        }

        __syncthreads();    // all reads of A[cur], B[cur], noise done
        if (r + 2 < ROUNDS) issue_b(Bcur, r + 2, tid);
        asm volatile("cp.async.commit_group;" ::: "memory");  // (possibly empty) keep counts
        if (r + 1 < ROUNDS) nsm[tid] = (int)noise[((r + 1) << 8) + tid];
    }
}

// ---------------- launch ----------------
extern "C" void kernel_launch(void* const* d_in, const int* in_sizes, int n_in,
                              void* d_out, int out_size) {
    const float* state = (const float*)d_in[0];
    const float* mats  = (const float*)d_in[1];
    const float* noise = (const float*)d_in[2];
    float* out = (float*)d_out;

    cvt_mats_kernel<<<ROUNDS * MAT_BYTES / 4 / 256, 256>>>(mats);

    cudaFuncSetAttribute(tenshash_kernel,
                         cudaFuncAttributeMaxDynamicSharedMemorySize, SMEM_TOTAL);
    tenshash_kernel<<<NTILES, 256, SMEM_TOTAL>>>(state, noise, out);
}

// round 3
// speedup vs baseline: 1.1365x; 1.1365x over previous
#include <cuda_runtime.h>
#include <cstdint>

#define ROUNDS 64
#define HID 256
#define BATCH 65536
#define TILE_M 128
#define NTILES (BATCH / TILE_M)      // 512
#define MAT_BYTES (HID * HID)        // 65536 s8 per round matrix

// Pre-converted, pre-swizzled s8 matrices (SMEM image layout), 4 MB. Lives in L2.
__device__ __align__(128) unsigned char g_mat[ROUNDS * MAT_BYTES];

// ---------------- SMEM layout ----------------
#define OF_NOISE 0
#define OF_A0    1024
#define OF_A1    (1024 + 32768)
#define OF_B0    (1024 + 2 * 32768)
#define OF_B1    (OF_B0 + 65536)
#define SMEM_TOTAL (OF_B1 + 65536)   // 197632 bytes

// ---------------- helpers ----------------
__device__ __forceinline__ uint32_t smem_u32(const void* p) {
    uint32_t a;
    asm("{ .reg .u64 t; cvta.to.shared.u64 t, %1; cvt.u32.u64 %0, t; }" : "=r"(a) : "l"(p));
    return a;
}

// byte address inside a [rows x 256B] tile with 16B-chunk XOR swizzle
__device__ __forceinline__ uint32_t swz(uint32_t row, uint32_t col) {
    return row * 256u + ((((col >> 4) ^ (row & 7u)) << 4) | (col & 15u));
}

__device__ __forceinline__ void ldm_x4(uint32_t addr, uint32_t& r0, uint32_t& r1,
                                       uint32_t& r2, uint32_t& r3) {
    asm volatile("ldmatrix.sync.aligned.m8n8.x4.shared.b16 {%0,%1,%2,%3}, [%4];"
                 : "=r"(r0), "=r"(r1), "=r"(r2), "=r"(r3) : "r"(addr));
}

__device__ __forceinline__ void mma_s8(int* c, uint32_t a0, uint32_t a1, uint32_t a2,
                                       uint32_t a3, uint32_t b0, uint32_t b1) {
    asm volatile(
        "mma.sync.aligned.m16n8k32.row.col.s32.s8.s8.s32 "
        "{%0,%1,%2,%3}, {%4,%5,%6,%7}, {%8,%9}, {%0,%1,%2,%3};"
        : "+r"(c[0]), "+r"(c[1]), "+r"(c[2]), "+r"(c[3])
        : "r"(a0), "r"(a1), "r"(a2), "r"(a3), "r"(b0), "r"(b1));
}

__device__ __forceinline__ void issue_b(uint32_t dst, int r, int tid) {
    const unsigned char* src = g_mat + (size_t)r * MAT_BYTES;
#pragma unroll
    for (int j = 0; j < 16; j++) {
        uint32_t off = (uint32_t)(tid + (j << 8)) << 4;
        asm volatile("cp.async.cg.shared.global [%0], [%1], 16;"
                     :: "r"(dst + off), "l"(src + off) : "memory");
    }
}

// ---------------- Kernel 1: f32 matrices -> s8 pre-swizzled image ----------------
__global__ void cvt_mats_kernel(const float* __restrict__ m) {
    uint32_t i = blockIdx.x * 256u + threadIdx.x;       // group of 4 elements
    const float4 v = *(const float4*)(m + (size_t)i * 4);
    uint32_t e0 = v.x > 0.5f ? 0x01u : (v.x < -0.5f ? 0xFFu : 0x00u);
    uint32_t e1 = v.y > 0.5f ? 0x01u : (v.y < -0.5f ? 0xFFu : 0x00u);
    uint32_t e2 = v.z > 0.5f ? 0x01u : (v.z < -0.5f ? 0xFFu : 0x00u);
    uint32_t e3 = v.w > 0.5f ? 0x01u : (v.w < -0.5f ? 0xFFu : 0x00u);
    uint32_t pk = e0 | (e1 << 8) | (e2 << 16) | (e3 << 24);
    uint32_t idx = i << 2;
    uint32_t r = idx >> 16, n = (idx >> 8) & 255u, k = idx & 255u;
    *(uint32_t*)(g_mat + (r << 16) + swz(n, k)) = pk;   // k%16 is 4-aligned here
}

// ---------------- Kernel 2: 64 sequential rounds per 128-row tile ----------------
// Warp tiling: warp w -> m-group mg = w&3 (rows mg*32..+32), n-half nh = w>>2
// (cols nh*128..+128). Each warp: m32 x n128, chunked as 2 x n64.
__global__ __launch_bounds__(256, 1)
void tenshash_kernel(const float* __restrict__ state,
                     const float* __restrict__ noise,
                     float* __restrict__ out) {
    extern __shared__ unsigned char smem[];
    uint32_t sb = smem_u32(smem);
    int tid = threadIdx.x, w = tid >> 5, l = tid & 31;
    int* nsm = (int*)(smem + OF_NOISE);
    const int gbase = blockIdx.x * TILE_M;
    const int mg = w & 3, nh = w >> 2;

    // stage noise[0]
    nsm[tid] = (int)noise[tid];

    // init A0 from state (float {0,1} -> s8), swizzled, u16-packed
    for (int i = tid; i < TILE_M * HID / 2; i += 256) {
        int row = i >> 7;
        int k = (i & 127) << 1;
        const float2 v = *(const float2*)(state + (size_t)(gbase + row) * HID + k);
        uint32_t b0 = v.x > 0.5f ? 1u : 0u;
        uint32_t b1 = v.y > 0.5f ? 1u : 0u;
        *(unsigned short*)(smem + OF_A0 + swz((uint32_t)row, (uint32_t)k)) =
            (unsigned short)(b0 | (b1 << 8));
    }

    // prologue: prefetch B for rounds 0 and 1
    issue_b(sb + OF_B0, 0, tid);
    asm volatile("cp.async.commit_group;" ::: "memory");
    issue_b(sb + OF_B1, 1, tid);
    asm volatile("cp.async.commit_group;" ::: "memory");

    // lane-invariant addressing pieces
    const uint32_t rowA0 = (uint32_t)(mg * 32) + (l & 15);        // A tile t=0
    const uint32_t rowA1 = rowA0 + 16;                            // A tile t=1
    const uint32_t sA0 = rowA0 & 7u, sA1 = rowA1 & 7u;
    const uint32_t aHalf = (uint32_t)(l >> 4);                    // k-chunk half
    const uint32_t bHalf = ((uint32_t)l >> 3) & 1u;
    const int erow0 = mg * 32 + (l >> 2);                         // epilogue rows
    const int ecol = nh * 128 + ((l & 3) << 1);

#pragma unroll 1
    for (int r = 0; r < ROUNDS; r++) {
        asm volatile("cp.async.wait_group 1;" ::: "memory");
        __syncthreads();    // B[r&1] ready; A[cur]/noise staged
        const uint32_t Acur = sb + ((r & 1) ? OF_A1 : OF_A0);
        const uint32_t AnxtOff = (r & 1) ? OF_A0 : OF_A1;
        const uint32_t Bcur = sb + ((r & 1) ? OF_B1 : OF_B0);
        const bool last = (r == ROUNDS - 1);

#pragma unroll 1
        for (int ch = 0; ch < 2; ch++) {           // two 64-col n-chunks
            int acc[2][8][4];
#pragma unroll
            for (int t = 0; t < 2; t++)
#pragma unroll
                for (int j = 0; j < 8; j++)
                    acc[t][j][0] = acc[t][j][1] = acc[t][j][2] = acc[t][j][3] = 0;

#pragma unroll
            for (int kk = 0; kk < 8; kk++) {       // K = 8 x k32
                uint32_t a0[4], a1[4];
                ldm_x4(Acur + rowA0 * 256u + ((((uint32_t)(2 * kk) + aHalf) ^ sA0) << 4),
                       a0[0], a0[1], a0[2], a0[3]);
                ldm_x4(Acur + rowA1 * 256u + ((((uint32_t)(2 * kk) + aHalf) ^ sA1) << 4),
                       a1[0], a1[1], a1[2], a1[3]);
                uint32_t bb[16];
#pragma unroll
                for (int p = 0; p < 4; p++) {      // 16 cols (2 n-tiles) per x4
                    uint32_t n = (uint32_t)(nh * 128 + ch * 64 + p * 16) +
                                 (((uint32_t)l >> 4) << 3) + (l & 7);
                    uint32_t cb = (uint32_t)(2 * kk) + bHalf;
                    ldm_x4(Bcur + n * 256u + ((cb ^ (n & 7u)) << 4),
                           bb[4 * p + 0], bb[4 * p + 1], bb[4 * p + 2], bb[4 * p + 3]);
                }
#pragma unroll
                for (int j = 0; j < 8; j++) {
                    int idx = 4 * (j >> 1) + 2 * (j & 1);
                    mma_s8(acc[0][j], a0[0], a0[1], a0[2], a0[3], bb[idx], bb[idx + 1]);
                    mma_s8(acc[1][j], a1[0], a1[1], a1[2], a1[3], bb[idx], bb[idx + 1]);
                }
            }

            // epilogue: v = (acc + noise) % 2 (C trunc == fmod), write next A / out
#pragma unroll
            for (int t = 0; t < 2; t++) {
#pragma unroll
                for (int j = 0; j < 8; j++) {
                    int col0 = ecol + (ch << 6) + (j << 3);
                    int n0 = nsm[col0], n1 = nsm[col0 + 1];
                    int r0loc = erow0 + t * 16, r1loc = r0loc + 8;
                    int v00 = (acc[t][j][0] + n0) % 2, v01 = (acc[t][j][1] + n1) % 2;
                    int v10 = (acc[t][j][2] + n0) % 2, v11 = (acc[t][j][3] + n1) % 2;
                    if (!last) {
                        *(unsigned short*)(smem + AnxtOff + swz((uint32_t)r0loc, (uint32_t)col0)) =
                            (unsigned short)((v00 & 255) | ((v01 & 255) << 8));
                        *(unsigned short*)(smem + AnxtOff + swz((uint32_t)r1loc, (uint32_t)col0)) =
                            (unsigned short)((v10 & 255) | ((v11 & 255) << 8));
                    } else {
                        float2 o0 = make_float2((float)v00, (float)v01);
                        float2 o1 = make_float2((float)v10, (float)v11);
                        *(float2*)(out + (size_t)(gbase + r0loc) * HID + col0) = o0;
                        *(float2*)(out + (size_t)(gbase + r1loc) * HID + col0) = o1;
                    }
                }
            }
        }

        __syncthreads();    // all reads of A[cur], B[cur], noise done
        if (r + 2 < ROUNDS) issue_b(Bcur, r + 2, tid);
        asm volatile("cp.async.commit_group;" ::: "memory");  // keep group counts
        if (r + 1 < ROUNDS) nsm[tid] = (int)noise[((r + 1) << 8) + tid];
    }
}

// ---------------- launch ----------------
extern "C" void kernel_launch(void* const* d_in, const int* in_sizes, int n_in,
                              void* d_out, int out_size) {
    const float* state = (const float*)d_in[0];
    const float* mats  = (const float*)d_in[1];
    const float* noise = (const float*)d_in[2];
    float* out = (float*)d_out;

    cvt_mats_kernel<<<ROUNDS * MAT_BYTES / 4 / 256, 256>>>(mats);

    cudaFuncSetAttribute(tenshash_kernel,
                         cudaFuncAttributeMaxDynamicSharedMemorySize, SMEM_TOTAL);
    tenshash_kernel<<<NTILES, 256, SMEM_TOTAL>>>(state, noise, out);
}

// round 4
// speedup vs baseline: 1.4091x; 1.2399x over previous
#include <cuda_runtime.h>
#include <cstdint>

#define ROUNDS 64
#define HID 256
#define BATCH 65536
#define TILE_M 128
#define NTILES (BATCH / TILE_M)      // 512
#define MAT_BYTES (HID * HID)        // 65536 s8 per round matrix

// Pre-converted, pre-swizzled s8 matrices (SMEM image layout), 4 MB. Lives in L2.
__device__ __align__(128) unsigned char g_mat[ROUNDS * MAT_BYTES];

// ---------------- SMEM layout (fits 2 CTAs/SM) ----------------
#define OF_NOISE 0
#define OF_A     1024
#define OF_B     (1024 + 32768)
#define SMEM_TOTAL (OF_B + 65536)    // 99328 bytes

// ---------------- helpers ----------------
__device__ __forceinline__ uint32_t smem_u32(const void* p) {
    uint32_t a;
    asm("{ .reg .u64 t; cvta.to.shared.u64 t, %1; cvt.u32.u64 %0, t; }" : "=r"(a) : "l"(p));
    return a;
}

// byte address inside a [rows x 256B] tile with 16B-chunk XOR swizzle
__device__ __forceinline__ uint32_t swz(uint32_t row, uint32_t col) {
    return row * 256u + ((((col >> 4) ^ (row & 7u)) << 4) | (col & 15u));
}

__device__ __forceinline__ void ldm_x4(uint32_t addr, uint32_t& r0, uint32_t& r1,
                                       uint32_t& r2, uint32_t& r3) {
    asm volatile("ldmatrix.sync.aligned.m8n8.x4.shared.b16 {%0,%1,%2,%3}, [%4];"
                 : "=r"(r0), "=r"(r1), "=r"(r2), "=r"(r3) : "r"(addr));
}

__device__ __forceinline__ void mma_s8(int* c, uint32_t a0, uint32_t a1, uint32_t a2,
                                       uint32_t a3, uint32_t b0, uint32_t b1) {
    asm volatile(
        "mma.sync.aligned.m16n8k32.row.col.s32.s8.s8.s32 "
        "{%0,%1,%2,%3}, {%4,%5,%6,%7}, {%8,%9}, {%0,%1,%2,%3};"
        : "+r"(c[0]), "+r"(c[1]), "+r"(c[2]), "+r"(c[3])
        : "r"(a0), "r"(a1), "r"(a2), "r"(a3), "r"(b0), "r"(b1));
}

__device__ __forceinline__ void issue_b(uint32_t dst, int r, int tid) {
    const unsigned char* src = g_mat + (size_t)r * MAT_BYTES;
#pragma unroll
    for (int j = 0; j < 16; j++) {
        uint32_t off = (uint32_t)(tid + (j << 8)) << 4;
        asm volatile("cp.async.cg.shared.global [%0], [%1], 16;"
                     :: "r"(dst + off), "l"(src + off) : "memory");
    }
}

// ---------------- Kernel 1: f32 matrices -> s8 pre-swizzled image ----------------
__global__ void cvt_mats_kernel(const float* __restrict__ m) {
    uint32_t i = blockIdx.x * 256u + threadIdx.x;       // group of 4 elements
    const float4 v = *(const float4*)(m + (size_t)i * 4);
    uint32_t e0 = v.x > 0.5f ? 0x01u : (v.x < -0.5f ? 0xFFu : 0x00u);
    uint32_t e1 = v.y > 0.5f ? 0x01u : (v.y < -0.5f ? 0xFFu : 0x00u);
    uint32_t e2 = v.z > 0.5f ? 0x01u : (v.z < -0.5f ? 0xFFu : 0x00u);
    uint32_t e3 = v.w > 0.5f ? 0x01u : (v.w < -0.5f ? 0xFFu : 0x00u);
    uint32_t pk = e0 | (e1 << 8) | (e2 << 16) | (e3 << 24);
    uint32_t idx = i << 2;
    uint32_t r = idx >> 16, n = (idx >> 8) & 255u, k = idx & 255u;
    *(uint32_t*)(g_mat + (r << 16) + swz(n, k)) = pk;   // k%16 is 4-aligned here
}

// ---------------- Kernel 2: 64 sequential rounds per 128-row tile ----------------
// Warp tiling: warp w -> m-group mg = w&3 (rows mg*32..+32), n-half nh = w>>2
// (cols nh*128..+128). Single A and B smem buffers; next-A staged in registers.
__global__ __launch_bounds__(256, 2)
void tenshash_kernel(const float* __restrict__ state,
                     const float* __restrict__ noise,
                     float* __restrict__ out) {
    extern __shared__ unsigned char smem[];
    uint32_t sb = smem_u32(smem);
    int tid = threadIdx.x, w = tid >> 5, l = tid & 31;
    int* nsm = (int*)(smem + OF_NOISE);
    const int gbase = blockIdx.x * TILE_M;
    const int mg = w & 3, nh = w >> 2;

    // stage noise[0]
    nsm[tid] = (int)noise[tid];

    // init A from state (float {0,1} -> s8), swizzled, u16-packed
    for (int i = tid; i < TILE_M * HID / 2; i += 256) {
        int row = i >> 7;
        int k = (i & 127) << 1;
        const float2 v = *(const float2*)(state + (size_t)(gbase + row) * HID + k);
        uint32_t b0 = v.x > 0.5f ? 1u : 0u;
        uint32_t b1 = v.y > 0.5f ? 1u : 0u;
        *(unsigned short*)(smem + OF_A + swz((uint32_t)row, (uint32_t)k)) =
            (unsigned short)(b0 | (b1 << 8));
    }

    // prologue: prefetch B for round 0
    issue_b(sb + OF_B, 0, tid);
    asm volatile("cp.async.commit_group;" ::: "memory");

    // lane-invariant addressing pieces
    const uint32_t rowA0 = (uint32_t)(mg * 32) + (l & 15);        // A tile t=0
    const uint32_t rowA1 = rowA0 + 16;                            // A tile t=1
    const uint32_t sA0 = rowA0 & 7u, sA1 = rowA1 & 7u;
    const uint32_t aHalf = (uint32_t)(l >> 4);                    // k-chunk half
    const uint32_t bHalf = ((uint32_t)l >> 3) & 1u;
    const int erow0 = mg * 32 + (l >> 2);                         // epilogue rows
    const int ecol = nh * 128 + ((l & 3) << 1);
    const uint32_t Acur = sb + OF_A;
    const uint32_t Bcur = sb + OF_B;

#pragma unroll 1
    for (int r = 0; r < ROUNDS; r++) {
        asm volatile("cp.async.wait_group 0;" ::: "memory");
        __syncthreads();    // B[r] ready; A stores and noise from r-1 visible
        const bool last = (r == ROUNDS - 1);
        uint32_t pk32[32];  // staged next-A: [ch*16 + t*8 + j]

#pragma unroll 1
        for (int ch = 0; ch < 2; ch++) {           // two 64-col n-chunks
            int acc[2][8][4];
#pragma unroll
            for (int t = 0; t < 2; t++)
#pragma unroll
                for (int j = 0; j < 8; j++)
                    acc[t][j][0] = acc[t][j][1] = acc[t][j][2] = acc[t][j][3] = 0;

#pragma unroll
            for (int kk = 0; kk < 8; kk++) {       // K = 8 x k32
                uint32_t a0[4], a1[4];
                ldm_x4(Acur + rowA0 * 256u + ((((uint32_t)(2 * kk) + aHalf) ^ sA0) << 4),
                       a0[0], a0[1], a0[2], a0[3]);
                ldm_x4(Acur + rowA1 * 256u + ((((uint32_t)(2 * kk) + aHalf) ^ sA1) << 4),
                       a1[0], a1[1], a1[2], a1[3]);
#pragma unroll
                for (int p = 0; p < 4; p++) {      // 16 cols (2 n-tiles) per x4
                    uint32_t bb[4];
                    uint32_t n = (uint32_t)(nh * 128 + ch * 64 + p * 16) +
                                 (((uint32_t)l >> 4) << 3) + (l & 7);
                    uint32_t cb = (uint32_t)(2 * kk) + bHalf;
                    ldm_x4(Bcur + n * 256u + ((cb ^ (n & 7u)) << 4),
                           bb[0], bb[1], bb[2], bb[3]);
                    mma_s8(acc[0][2 * p + 0], a0[0], a0[1], a0[2], a0[3], bb[0], bb[1]);
                    mma_s8(acc[0][2 * p + 1], a0[0], a0[1], a0[2], a0[3], bb[2], bb[3]);
                    mma_s8(acc[1][2 * p + 0], a1[0], a1[1], a1[2], a1[3], bb[0], bb[1]);
                    mma_s8(acc[1][2 * p + 1], a1[0], a1[1], a1[2], a1[3], bb[2], bb[3]);
                }
            }

            // epilogue: v = (acc + noise) % 2 (C trunc == fmod)
#pragma unroll
            for (int t = 0; t < 2; t++) {
#pragma unroll
                for (int j = 0; j < 8; j++) {
                    int col0 = ecol + (ch << 6) + (j << 3);
                    int n0 = nsm[col0], n1 = nsm[col0 + 1];
                    int v00 = (acc[t][j][0] + n0) % 2, v01 = (acc[t][j][1] + n1) % 2;
                    int v10 = (acc[t][j][2] + n0) % 2, v11 = (acc[t][j][3] + n1) % 2;
                    if (!last) {
                        pk32[ch * 16 + t * 8 + j] =
                            (v00 & 255) | ((v01 & 255) << 8) |
                            ((v10 & 255) << 16) | ((uint32_t)(v11 & 255) << 24);
                    } else {
                        float2 o0 = make_float2((float)v00, (float)v01);
                        float2 o1 = make_float2((float)v10, (float)v11);
                        int r0loc = erow0 + t * 16, r1loc = r0loc + 8;
                        *(float2*)(out + (size_t)(gbase + r0loc) * HID + col0) = o0;
                        *(float2*)(out + (size_t)(gbase + r1loc) * HID + col0) = o1;
                    }
                }
            }
        }

        __syncthreads();    // all reads of A, B, noise for round r done
        if (!last) {
            // issue next B load (into same single buffer)
            issue_b(Bcur, r + 1, tid);
            asm volatile("cp.async.commit_group;" ::: "memory");
            // store staged next-A to SMEM
#pragma unroll
            for (int ch = 0; ch < 2; ch++)
#pragma unroll
                for (int t = 0; t < 2; t++)
#pragma unroll
                    for (int j = 0; j < 8; j++) {
                        uint32_t v = pk32[ch * 16 + t * 8 + j];
                        int col0 = ecol + (ch << 6) + (j << 3);
                        int r0loc = erow0 + t * 16, r1loc = r0loc + 8;
                        *(unsigned short*)(smem + OF_A + swz((uint32_t)r0loc, (uint32_t)col0)) =
                            (unsigned short)(v & 0xFFFFu);
                        *(unsigned short*)(smem + OF_A + swz((uint32_t)r1loc, (uint32_t)col0)) =
                            (unsigned short)(v >> 16);
                    }
            // stage next round's noise
            nsm[tid] = (int)noise[((r + 1) << 8) + tid];
        }
    }
}

// ---------------- launch ----------------
extern "C" void kernel_launch(void* const* d_in, const int* in_sizes, int n_in,
                              void* d_out, int out_size) {
    const float* state = (const float*)d_in[0];
    const float* mats  = (const float*)d_in[1];
    const float* noise = (const float*)d_in[2];
    float* out = (float*)d_out;

    cvt_mats_kernel<<<ROUNDS * MAT_BYTES / 4 / 256, 256>>>(mats);

    cudaFuncSetAttribute(tenshash_kernel,
                         cudaFuncAttributeMaxDynamicSharedMemorySize, SMEM_TOTAL);
    tenshash_kernel<<<NTILES, 256, SMEM_TOTAL>>>(state, noise, out);
}